// round 1
// baseline (speedup 1.0000x reference)
#include <cuda_runtime.h>
#include <math.h>

#define NN   50000
#define EE   800000
#define IND  128
#define HIDD 256
#define OUTD 40
#define TOT  (EE + NN)
#define BN_EPS 1e-5f

// ---------------- scratch (device globals: alloc-guard compliant) ----------------
__device__ __align__(16) float g_t1[(size_t)NN * HIDD];   // transform output
__device__ __align__(16) float g_t2[(size_t)NN * HIDD];   // aggregation output
__device__ float g_dinv[NN];
__device__ int   g_deg[NN];
__device__ int   g_cnt[NN];          // counts, then cursor
__device__ int   g_off[NN + 1];
__device__ int   g_row[EE];
__device__ int   g_col[EE];
__device__ int   g_csr_col[TOT];
__device__ float g_csr_w[TOT];
__device__ float g_sum[HIDD];
__device__ float g_sumsq[HIDD];
__device__ float g_bn_s[HIDD];       // rstd*gamma
__device__ float g_bn_t[HIDD];       // beta - mu*rstd*gamma
__device__ int   g_is64;

static inline int cdiv(int a, int b) { return (a + b - 1) / b; }

// ---------------- edge-index dtype detection + conversion ----------------
__global__ void k_detect(const void* ei) {
    // If data is int64, every 8-byte value is a valid node id (< NN).
    // If int32, an 8-byte read combines two random ids -> almost surely >= 2^32.
    const unsigned long long* p = (const unsigned long long*)ei;
    int is64 = 1;
    for (int i = 0; i < 8; i++) if (p[i] >= (unsigned long long)NN) is64 = 0;
    g_is64 = is64;
}

__global__ void k_convert(const void* ei) {
    int e = blockIdx.x * blockDim.x + threadIdx.x;
    if (e >= EE) return;
    if (g_is64) {
        const long long* p = (const long long*)ei;
        g_row[e] = (int)p[e];
        g_col[e] = (int)p[EE + e];
    } else {
        const int* p = (const int*)ei;
        g_row[e] = p[e];
        g_col[e] = p[EE + e];
    }
}

// ---------------- degree / norm / CSR build ----------------
__global__ void k_init_counts() {
    int i = blockIdx.x * blockDim.x + threadIdx.x;
    if (i >= NN) return;
    g_deg[i] = 1;   // self-loop
    g_cnt[i] = 1;   // self-loop slot
}

__global__ void k_deg_count() {
    int e = blockIdx.x * blockDim.x + threadIdx.x;
    if (e >= EE) return;
    atomicAdd(&g_deg[g_col[e]], 1);   // deg = segment_sum over col
    atomicAdd(&g_cnt[g_row[e]], 1);   // CSR bucket sizes keyed by destination row
}

__global__ void k_dinv() {
    int i = blockIdx.x * blockDim.x + threadIdx.x;
    if (i >= NN) return;
    g_dinv[i] = rsqrtf((float)g_deg[i]);
}

// single-block exclusive scan of g_cnt -> g_off, then reset g_cnt to 0
__global__ void k_scan() {
    __shared__ int part[1024];
    int t = threadIdx.x;
    const int CH = (NN + 1023) / 1024;
    int b = t * CH;
    int e = min(NN, b + CH);
    int s = 0;
    for (int i = b; i < e; i++) s += g_cnt[i];
    part[t] = s;
    __syncthreads();
    for (int off = 1; off < 1024; off <<= 1) {
        int v = (t >= off) ? part[t - off] : 0;
        __syncthreads();
        part[t] += v;
        __syncthreads();
    }
    int pre = (t == 0) ? 0 : part[t - 1];
    for (int i = b; i < e; i++) {
        g_off[i] = pre;
        pre += g_cnt[i];
    }
    if (t == 1023) g_off[NN] = part[1023];
    __syncthreads();
    for (int i = b; i < e; i++) g_cnt[i] = 0;
}

__global__ void k_fill() {
    int idx = blockIdx.x * blockDim.x + threadIdx.x;
    if (idx >= TOT) return;
    int r, c; float w;
    if (idx < EE) {
        r = g_row[idx];
        c = g_col[idx];
        w = g_dinv[r] * g_dinv[c];
    } else {
        r = idx - EE;
        c = r;
        float d = g_dinv[r];
        w = d * d;
    }
    int pos = g_off[r] + atomicAdd(&g_cnt[r], 1);
    g_csr_col[pos] = c;
    g_csr_w[pos]   = w;
}

// ---------------- GEMM: C[M,Ncols] = op(A[M,K]) @ B[K,Ncols] ----------------
// FUSE: a' = relu(a * g_bn_s[k] + g_bn_t[k])   (BN+ReLU folded into A-load)
template <bool FUSE>
__global__ void __launch_bounds__(256) k_gemm(
    const float* __restrict__ A, const float* __restrict__ B,
    float* __restrict__ C, int M, int K, int Ncols)
{
    constexpr int BM = 128, BN = 64, BK = 16, TM = 8, TN = 4;
    __shared__ float As[BK][BM + 1];
    __shared__ float Bs[BK][BN];

    int tid = threadIdx.x;
    int bm = blockIdx.y * BM;
    int bn = blockIdx.x * BN;
    int tx = tid & 15;          // BN/TN = 16
    int ty = tid >> 4;          // BM/TM = 16

    float acc[TM][TN];
#pragma unroll
    for (int i = 0; i < TM; i++)
#pragma unroll
        for (int j = 0; j < TN; j++) acc[i][j] = 0.f;

    for (int k0 = 0; k0 < K; k0 += BK) {
        // load A tile (BM x BK) as 2 float4 per thread, store transposed
#pragma unroll
        for (int rep = 0; rep < 2; rep++) {
            int q = tid + rep * 256;
            int ar = q >> 2;          // 0..127
            int ac4 = q & 3;          // 0..3
            int gm = bm + ar;
            int gk = k0 + ac4 * 4;
            float4 v = make_float4(0.f, 0.f, 0.f, 0.f);
            if (gm < M)
                v = *reinterpret_cast<const float4*>(A + (size_t)gm * K + gk);
            if (FUSE) {
                v.x = fmaxf(0.f, fmaf(v.x, g_bn_s[gk + 0], g_bn_t[gk + 0]));
                v.y = fmaxf(0.f, fmaf(v.y, g_bn_s[gk + 1], g_bn_t[gk + 1]));
                v.z = fmaxf(0.f, fmaf(v.z, g_bn_s[gk + 2], g_bn_t[gk + 2]));
                v.w = fmaxf(0.f, fmaf(v.w, g_bn_s[gk + 3], g_bn_t[gk + 3]));
            }
            As[ac4 * 4 + 0][ar] = v.x;
            As[ac4 * 4 + 1][ar] = v.y;
            As[ac4 * 4 + 2][ar] = v.z;
            As[ac4 * 4 + 3][ar] = v.w;
        }
        // load B tile (BK x BN): 1 float4 per thread
        {
            int br = tid >> 4;        // 0..15
            int bc4 = tid & 15;       // 0..15
            int gk = k0 + br;
            int gn = bn + bc4 * 4;
            float4 v = make_float4(0.f, 0.f, 0.f, 0.f);
            if (gn < Ncols)           // Ncols is a multiple of 4
                v = *reinterpret_cast<const float4*>(B + (size_t)gk * Ncols + gn);
            Bs[br][bc4 * 4 + 0] = v.x;
            Bs[br][bc4 * 4 + 1] = v.y;
            Bs[br][bc4 * 4 + 2] = v.z;
            Bs[br][bc4 * 4 + 3] = v.w;
        }
        __syncthreads();

#pragma unroll
        for (int kk = 0; kk < BK; kk++) {
            float a[TM], b[TN];
#pragma unroll
            for (int i = 0; i < TM; i++) a[i] = As[kk][ty * TM + i];
            float4 bv = *reinterpret_cast<const float4*>(&Bs[kk][tx * TN]);
            b[0] = bv.x; b[1] = bv.y; b[2] = bv.z; b[3] = bv.w;
#pragma unroll
            for (int i = 0; i < TM; i++)
#pragma unroll
                for (int j = 0; j < TN; j++)
                    acc[i][j] = fmaf(a[i], b[j], acc[i][j]);
        }
        __syncthreads();
    }

#pragma unroll
    for (int i = 0; i < TM; i++) {
        int gm = bm + ty * TM + i;
        if (gm >= M) continue;
#pragma unroll
        for (int j = 0; j < TN; j++) {
            int gn = bn + tx * TN + j;
            if (gn < Ncols) C[(size_t)gm * Ncols + gn] = acc[i][j];
        }
    }
}

// ---------------- aggregation: out[i] = sum_{p in CSR(i)} w_p * h[col_p] + bias ----------------
__global__ void __launch_bounds__(64) k_agg256(
    const float* __restrict__ h, const float* __restrict__ bias,
    float* __restrict__ out)
{
    int i = blockIdx.x;
    int t = threadIdx.x;        // 0..63, owns 4 features
    float4 acc = make_float4(0.f, 0.f, 0.f, 0.f);
    int beg = g_off[i], end = g_off[i + 1];
    for (int p = beg; p < end; p++) {
        int   c = __ldg(&g_csr_col[p]);
        float w = __ldg(&g_csr_w[p]);
        float4 v = *reinterpret_cast<const float4*>(h + (size_t)c * HIDD + t * 4);
        acc.x = fmaf(w, v.x, acc.x);
        acc.y = fmaf(w, v.y, acc.y);
        acc.z = fmaf(w, v.z, acc.z);
        acc.w = fmaf(w, v.w, acc.w);
    }
    float4 b = *reinterpret_cast<const float4*>(bias + t * 4);
    acc.x += b.x; acc.y += b.y; acc.z += b.z; acc.w += b.w;
    *reinterpret_cast<float4*>(out + (size_t)i * HIDD + t * 4) = acc;
}

__global__ void __launch_bounds__(64) k_agg40(
    const float* __restrict__ h, const float* __restrict__ bias,
    float* __restrict__ out)
{
    int i = blockIdx.x;
    int t = threadIdx.x;
    if (t >= OUTD) return;
    float acc = 0.f;
    int beg = g_off[i], end = g_off[i + 1];
    for (int p = beg; p < end; p++) {
        int   c = __ldg(&g_csr_col[p]);
        float w = __ldg(&g_csr_w[p]);
        acc = fmaf(w, h[(size_t)c * OUTD + t], acc);
    }
    out[(size_t)i * OUTD + t] = acc + bias[t];
}

// ---------------- batchnorm stats ----------------
__global__ void k_zero_stats() {
    int c = threadIdx.x;
    g_sum[c] = 0.f;
    g_sumsq[c] = 0.f;
}

__global__ void __launch_bounds__(256) k_stats(const float* __restrict__ h) {
    int c = threadIdx.x;   // 256 columns
    int rows_per_block = (NN + gridDim.x - 1) / gridDim.x;
    int r0 = blockIdx.x * rows_per_block;
    int r1 = min(NN, r0 + rows_per_block);
    float s = 0.f, ss = 0.f;
    for (int r = r0; r < r1; r++) {
        float v = h[(size_t)r * HIDD + c];
        s += v;
        ss = fmaf(v, v, ss);
    }
    atomicAdd(&g_sum[c], s);
    atomicAdd(&g_sumsq[c], ss);
}

__global__ void k_bn_finalize(const float* __restrict__ gamma,
                              const float* __restrict__ beta) {
    int c = threadIdx.x;
    float mu = g_sum[c] * (1.f / NN);
    float var = g_sumsq[c] * (1.f / NN) - mu * mu;
    float rstd = rsqrtf(var + BN_EPS);
    float sc = rstd * gamma[c];
    g_bn_s[c] = sc;
    g_bn_t[c] = beta[c] - mu * sc;
}

// ---------------- log_softmax over 40 classes (one warp per row) ----------------
__global__ void k_logsoftmax(const float* __restrict__ in, float* __restrict__ out) {
    int warp = (blockIdx.x * blockDim.x + threadIdx.x) >> 5;
    int lane = threadIdx.x & 31;
    if (warp >= NN) return;
    const float* r = in + (size_t)warp * OUTD;
    float v0 = (lane < OUTD) ? r[lane] : -INFINITY;
    float v1 = (lane + 32 < OUTD) ? r[lane + 32] : -INFINITY;
    float m = fmaxf(v0, v1);
#pragma unroll
    for (int off = 16; off > 0; off >>= 1)
        m = fmaxf(m, __shfl_xor_sync(0xFFFFFFFFu, m, off));
    float s = 0.f;
    if (lane < OUTD)      s += expf(v0 - m);
    if (lane + 32 < OUTD) s += expf(v1 - m);
#pragma unroll
    for (int off = 16; off > 0; off >>= 1)
        s += __shfl_xor_sync(0xFFFFFFFFu, s, off);
    float l = m + logf(s);
    if (lane < OUTD)      out[(size_t)warp * OUTD + lane] = v0 - l;
    if (lane + 32 < OUTD) out[(size_t)warp * OUTD + lane + 32] = v1 - l;
}

// ---------------- launch ----------------
extern "C" void kernel_launch(void* const* d_in, const int* in_sizes, int n_in,
                              void* d_out, int out_size) {
    const float* x     = (const float*)d_in[0];
    const void*  ei    = d_in[1];
    const float* W1    = (const float*)d_in[2];
    const float* b1    = (const float*)d_in[3];
    const float* W2    = (const float*)d_in[4];
    const float* b2    = (const float*)d_in[5];
    const float* W3    = (const float*)d_in[6];
    const float* b3    = (const float*)d_in[7];
    const float* gamma = (const float*)d_in[8];
    const float* beta  = (const float*)d_in[9];
    float* out = (float*)d_out;

    float *t1, *t2;
    cudaGetSymbolAddress((void**)&t1, g_t1);
    cudaGetSymbolAddress((void**)&t2, g_t2);

    // ---- graph preprocessing ----
    k_detect<<<1, 1>>>(ei);
    k_convert<<<cdiv(EE, 256), 256>>>(ei);
    k_init_counts<<<cdiv(NN, 256), 256>>>();
    k_deg_count<<<cdiv(EE, 256), 256>>>();
    k_dinv<<<cdiv(NN, 256), 256>>>();
    k_scan<<<1, 1024>>>();
    k_fill<<<cdiv(TOT, 256), 256>>>();

    dim3 g256(cdiv(HIDD, 64), cdiv(NN, 128));
    dim3 g40(cdiv(OUTD, 64), cdiv(NN, 128));

    // ---- layer 1 ----
    k_gemm<false><<<g256, 256>>>(x, W1, t1, NN, IND, HIDD);
    k_agg256<<<NN, 64>>>(t1, b1, t2);
    k_zero_stats<<<1, HIDD>>>();
    k_stats<<<256, HIDD>>>(t2);
    k_bn_finalize<<<1, HIDD>>>(gamma, beta);

    // ---- layer 2 (BN+ReLU fused into GEMM A-load) ----
    k_gemm<true><<<g256, 256>>>(t2, W2, t1, NN, HIDD, HIDD);
    k_agg256<<<NN, 64>>>(t1, b2, t2);
    k_zero_stats<<<1, HIDD>>>();
    k_stats<<<256, HIDD>>>(t2);
    k_bn_finalize<<<1, HIDD>>>(gamma, beta);

    // ---- layer 3 ----
    k_gemm<true><<<g40, 256>>>(t2, W3, t1, NN, HIDD, OUTD);
    k_agg40<<<NN, 64>>>(t1, b3, t2);

    // ---- log_softmax ----
    k_logsoftmax<<<cdiv(NN * 32, 256), 256>>>(t2, out);
}

// round 2
// speedup vs baseline: 1.3641x; 1.3641x over previous
#include <cuda_runtime.h>
#include <math.h>
#include <stdint.h>

#define NN   50000
#define EE   800000
#define IND  128
#define HIDD 256
#define OUTD 40
#define TOT  (EE + NN)
#define BN_EPS 1e-5f

// ---------------- scratch (device globals: alloc-guard compliant) ----------------
__device__ __align__(16) float g_t1[(size_t)NN * HIDD];   // transform / agg ping
__device__ __align__(16) float g_t2[(size_t)NN * HIDD];   // pong
__device__ float g_dinv[NN];
__device__ int   g_deg[NN];
__device__ int   g_cnt[NN];          // counts, then cursor
__device__ int   g_off[NN + 1];
__device__ int   g_row[EE];
__device__ int   g_col[EE];
__device__ int   g_csr_col[TOT];
__device__ float g_csr_w[TOT];
__device__ float g_sum[HIDD];
__device__ float g_sumsq[HIDD];
__device__ float g_bn_s[HIDD];       // rstd*gamma
__device__ float g_bn_t[HIDD];       // beta - mu*rstd*gamma
__device__ int   g_is64;

static inline int cdiv(int a, int b) { return (a + b - 1) / b; }

// ---------------- tf32 helpers ----------------
__device__ __forceinline__ float to_tf32(float x) {
    uint32_t u;
    asm("cvt.rna.tf32.f32 %0, %1;" : "=r"(u) : "f"(x));
    return __uint_as_float(u);
}

__device__ __forceinline__ void mma_tf32(float c[4], const uint32_t a[4], const uint32_t b[2]) {
    asm volatile(
        "mma.sync.aligned.m16n8k8.row.col.f32.tf32.tf32.f32 "
        "{%0,%1,%2,%3}, {%4,%5,%6,%7}, {%8,%9}, {%0,%1,%2,%3};\n"
        : "+f"(c[0]), "+f"(c[1]), "+f"(c[2]), "+f"(c[3])
        : "r"(a[0]), "r"(a[1]), "r"(a[2]), "r"(a[3]), "r"(b[0]), "r"(b[1]));
}

// ---------------- edge-index dtype detection + conversion ----------------
__global__ void k_detect(const void* ei) {
    const unsigned long long* p = (const unsigned long long*)ei;
    int is64 = 1;
    for (int i = 0; i < 8; i++) if (p[i] >= (unsigned long long)NN) is64 = 0;
    g_is64 = is64;
}

__global__ void k_init_counts() {
    int i = blockIdx.x * blockDim.x + threadIdx.x;
    if (i >= NN) return;
    g_deg[i] = 1;   // self-loop
    g_cnt[i] = 1;   // self-loop slot
}

// fused convert + degree count (one pass over edge_index)
__global__ void k_convert_deg(const void* ei) {
    int e = blockIdx.x * blockDim.x + threadIdx.x;
    if (e >= EE) return;
    int r, c;
    if (g_is64) {
        const long long* p = (const long long*)ei;
        r = (int)p[e];
        c = (int)p[EE + e];
    } else {
        const int* p = (const int*)ei;
        r = p[e];
        c = p[EE + e];
    }
    g_row[e] = r;
    g_col[e] = c;
    atomicAdd(&g_deg[c], 1);   // deg = segment_sum over col
    atomicAdd(&g_cnt[r], 1);   // CSR bucket sizes keyed by destination row
}

__global__ void k_dinv() {
    int i = blockIdx.x * blockDim.x + threadIdx.x;
    if (i >= NN) return;
    g_dinv[i] = rsqrtf((float)g_deg[i]);
}

// single-block exclusive scan of g_cnt -> g_off, then reset g_cnt to 0
__global__ void k_scan() {
    __shared__ int part[1024];
    int t = threadIdx.x;
    const int CH = (NN + 1023) / 1024;
    int b = t * CH;
    int e = min(NN, b + CH);
    int s = 0;
    for (int i = b; i < e; i++) s += g_cnt[i];
    part[t] = s;
    __syncthreads();
    for (int off = 1; off < 1024; off <<= 1) {
        int v = (t >= off) ? part[t - off] : 0;
        __syncthreads();
        part[t] += v;
        __syncthreads();
    }
    int pre = (t == 0) ? 0 : part[t - 1];
    for (int i = b; i < e; i++) {
        g_off[i] = pre;
        pre += g_cnt[i];
    }
    if (t == 1023) g_off[NN] = part[1023];
    __syncthreads();
    for (int i = b; i < e; i++) g_cnt[i] = 0;
}

__global__ void k_fill() {
    int idx = blockIdx.x * blockDim.x + threadIdx.x;
    if (idx >= TOT) return;
    int r, c; float w;
    if (idx < EE) {
        r = g_row[idx];
        c = g_col[idx];
        w = g_dinv[r] * g_dinv[c];
    } else {
        r = idx - EE;
        c = r;
        float d = g_dinv[r];
        w = d * d;
    }
    int pos = g_off[r] + atomicAdd(&g_cnt[r], 1);
    g_csr_col[pos] = c;
    g_csr_w[pos]   = w;
}

// ---------------- tensor-core GEMM: C = op(A[M,K]) @ B[K,Ncols] (+bias) ----------------
// FUSE: a' = relu(a * g_bn_s[k] + g_bn_t[k]) folded into A smem store.
template <bool FUSE, bool BIAS>
__global__ void __launch_bounds__(256) k_gemm_tc(
    const float* __restrict__ A, const float* __restrict__ B,
    const float* __restrict__ bias, float* __restrict__ C,
    int M, int K, int Ncols)
{
    constexpr int BM = 128, BN = 64, BK = 32;
    constexpr int ASTR = 36;   // 128B-pad: bank = (4m+k)%32, conflict-free frags
    constexpr int BSTR = 68;   // bank = (4k+n)%32, conflict-free frags
    __shared__ float As[BM * ASTR];
    __shared__ float Bs[BK * BSTR];

    const int tid  = threadIdx.x;
    const int warp = tid >> 5, lane = tid & 31;
    const int gid  = lane >> 2, tg = lane & 3;   // groupID / thread-in-group
    const int wm   = (warp & 3) * 32;            // 4 warps along M
    const int wn   = (warp >> 2) * 32;           // 2 warps along N
    const int bm   = blockIdx.y * BM, bn = blockIdx.x * BN;

    float c[2][4][4];
#pragma unroll
    for (int i = 0; i < 2; i++)
#pragma unroll
        for (int j = 0; j < 4; j++)
#pragma unroll
            for (int q = 0; q < 4; q++) c[i][j][q] = 0.f;

    float4 areg[4];
    float  breg[8];
    int kload = 0;

    // ---- prologue: load first tile to regs ----
#pragma unroll
    for (int r = 0; r < 4; r++) {
        int idx = tid + r * 256;
        int m = idx >> 3, c4 = idx & 7;
        int gm = bm + m;
        float4 v = make_float4(0.f, 0.f, 0.f, 0.f);
        if (gm < M) v = *reinterpret_cast<const float4*>(A + (size_t)gm * K + c4 * 4);
        areg[r] = v;
    }
#pragma unroll
    for (int r = 0; r < 8; r++) {
        int idx = tid + r * 256;
        int kk = idx >> 6, n = idx & 63;
        breg[r] = (bn + n < Ncols) ? B[(size_t)kk * Ncols + bn + n] : 0.f;
    }

    for (int k0 = 0; k0 < K; k0 += BK) {
        // ---- store staged regs to smem (FUSE + tf32 convert) ----
#pragma unroll
        for (int r = 0; r < 4; r++) {
            int idx = tid + r * 256;
            int m = idx >> 3, c4 = idx & 7;
            float4 v = areg[r];
            if (FUSE) {
                int gk = kload + c4 * 4;
                v.x = fmaxf(0.f, fmaf(v.x, g_bn_s[gk + 0], g_bn_t[gk + 0]));
                v.y = fmaxf(0.f, fmaf(v.y, g_bn_s[gk + 1], g_bn_t[gk + 1]));
                v.z = fmaxf(0.f, fmaf(v.z, g_bn_s[gk + 2], g_bn_t[gk + 2]));
                v.w = fmaxf(0.f, fmaf(v.w, g_bn_s[gk + 3], g_bn_t[gk + 3]));
            }
            float4 w = make_float4(to_tf32(v.x), to_tf32(v.y), to_tf32(v.z), to_tf32(v.w));
            *reinterpret_cast<float4*>(&As[m * ASTR + c4 * 4]) = w;
        }
#pragma unroll
        for (int r = 0; r < 8; r++) {
            int idx = tid + r * 256;
            int kk = idx >> 6, n = idx & 63;
            Bs[kk * BSTR + n] = to_tf32(breg[r]);
        }
        __syncthreads();

        // ---- prefetch next tile into regs ----
        bool has_next = (k0 + BK < K);
        if (has_next) {
            int kn = k0 + BK;
            kload = kn;
#pragma unroll
            for (int r = 0; r < 4; r++) {
                int idx = tid + r * 256;
                int m = idx >> 3, c4 = idx & 7;
                int gm = bm + m;
                float4 v = make_float4(0.f, 0.f, 0.f, 0.f);
                if (gm < M) v = *reinterpret_cast<const float4*>(A + (size_t)gm * K + kn + c4 * 4);
                areg[r] = v;
            }
#pragma unroll
            for (int r = 0; r < 8; r++) {
                int idx = tid + r * 256;
                int kk = idx >> 6, n = idx & 63;
                breg[r] = (bn + n < Ncols) ? B[(size_t)(kn + kk) * Ncols + bn + n] : 0.f;
            }
        }

        // ---- compute on current smem tile ----
#pragma unroll
        for (int kc = 0; kc < 4; kc++) {
            uint32_t a[2][4], b[4][2];
            int kb = kc * 8 + tg;
#pragma unroll
            for (int am = 0; am < 2; am++) {
                int mr = wm + am * 16 + gid;
                a[am][0] = __float_as_uint(As[mr * ASTR + kb]);
                a[am][1] = __float_as_uint(As[(mr + 8) * ASTR + kb]);
                a[am][2] = __float_as_uint(As[mr * ASTR + kb + 4]);
                a[am][3] = __float_as_uint(As[(mr + 8) * ASTR + kb + 4]);
            }
#pragma unroll
            for (int bi = 0; bi < 4; bi++) {
                int nc = wn + bi * 8 + gid;
                b[bi][0] = __float_as_uint(Bs[kb * BSTR + nc]);
                b[bi][1] = __float_as_uint(Bs[(kb + 4) * BSTR + nc]);
            }
#pragma unroll
            for (int am = 0; am < 2; am++)
#pragma unroll
                for (int bi = 0; bi < 4; bi++)
                    mma_tf32(c[am][bi], a[am], b[bi]);
        }
        __syncthreads();
    }

    // ---- epilogue ----
#pragma unroll
    for (int am = 0; am < 2; am++) {
#pragma unroll
        for (int bi = 0; bi < 4; bi++) {
            int row = bm + wm + am * 16 + gid;
            int col = bn + wn + bi * 8 + 2 * tg;
            float bv0 = 0.f, bv1 = 0.f;
            if (BIAS) {
                if (col < Ncols)     bv0 = bias[col];
                if (col + 1 < Ncols) bv1 = bias[col + 1];
            }
            if (row < M) {
                if (col < Ncols)     C[(size_t)row * Ncols + col]     = c[am][bi][0] + bv0;
                if (col + 1 < Ncols) C[(size_t)row * Ncols + col + 1] = c[am][bi][1] + bv1;
            }
            if (row + 8 < M) {
                if (col < Ncols)     C[(size_t)(row + 8) * Ncols + col]     = c[am][bi][2] + bv0;
                if (col + 1 < Ncols) C[(size_t)(row + 8) * Ncols + col + 1] = c[am][bi][3] + bv1;
            }
        }
    }
}

// ---------------- aggregation: out[i] = sum_p w_p * h[col_p] (+bias), float4 lanes ----------------
template <int F4, bool BIAS>
__global__ void __launch_bounds__(F4) k_agg_v(
    const float* __restrict__ h, const float* __restrict__ bias,
    float* __restrict__ out)
{
    const int F = F4 * 4;
    int i = blockIdx.x;
    int t = threadIdx.x;
    float4 acc = make_float4(0.f, 0.f, 0.f, 0.f);
    int p = g_off[i], end = g_off[i + 1];
    for (; p + 1 < end; p += 2) {
        int   c0 = __ldg(&g_csr_col[p]);
        int   c1 = __ldg(&g_csr_col[p + 1]);
        float w0 = __ldg(&g_csr_w[p]);
        float w1 = __ldg(&g_csr_w[p + 1]);
        float4 v0 = *reinterpret_cast<const float4*>(h + (size_t)c0 * F + t * 4);
        float4 v1 = *reinterpret_cast<const float4*>(h + (size_t)c1 * F + t * 4);
        acc.x = fmaf(w0, v0.x, fmaf(w1, v1.x, acc.x));
        acc.y = fmaf(w0, v0.y, fmaf(w1, v1.y, acc.y));
        acc.z = fmaf(w0, v0.z, fmaf(w1, v1.z, acc.z));
        acc.w = fmaf(w0, v0.w, fmaf(w1, v1.w, acc.w));
    }
    if (p < end) {
        int   c0 = __ldg(&g_csr_col[p]);
        float w0 = __ldg(&g_csr_w[p]);
        float4 v0 = *reinterpret_cast<const float4*>(h + (size_t)c0 * F + t * 4);
        acc.x = fmaf(w0, v0.x, acc.x);
        acc.y = fmaf(w0, v0.y, acc.y);
        acc.z = fmaf(w0, v0.z, acc.z);
        acc.w = fmaf(w0, v0.w, acc.w);
    }
    if (BIAS) {
        float4 b = *reinterpret_cast<const float4*>(bias + t * 4);
        acc.x += b.x; acc.y += b.y; acc.z += b.z; acc.w += b.w;
    }
    *reinterpret_cast<float4*>(out + (size_t)i * F + t * 4) = acc;
}

__global__ void __launch_bounds__(64) k_agg40(
    const float* __restrict__ h, const float* __restrict__ bias,
    float* __restrict__ out)
{
    int i = blockIdx.x;
    int t = threadIdx.x;
    if (t >= OUTD) return;
    float acc = 0.f;
    int p = g_off[i], end = g_off[i + 1];
    for (; p + 1 < end; p += 2) {
        int   c0 = __ldg(&g_csr_col[p]);
        int   c1 = __ldg(&g_csr_col[p + 1]);
        float w0 = __ldg(&g_csr_w[p]);
        float w1 = __ldg(&g_csr_w[p + 1]);
        acc = fmaf(w0, h[(size_t)c0 * OUTD + t], fmaf(w1, h[(size_t)c1 * OUTD + t], acc));
    }
    if (p < end) {
        int   c0 = __ldg(&g_csr_col[p]);
        float w0 = __ldg(&g_csr_w[p]);
        acc = fmaf(w0, h[(size_t)c0 * OUTD + t], acc);
    }
    out[(size_t)i * OUTD + t] = acc + bias[t];
}

// ---------------- batchnorm stats ----------------
__global__ void k_zero_stats() {
    int c = threadIdx.x;
    g_sum[c] = 0.f;
    g_sumsq[c] = 0.f;
}

__global__ void __launch_bounds__(256) k_stats(const float* __restrict__ h) {
    int c = threadIdx.x;
    int rows_per_block = (NN + gridDim.x - 1) / gridDim.x;
    int r0 = blockIdx.x * rows_per_block;
    int r1 = min(NN, r0 + rows_per_block);
    float s = 0.f, ss = 0.f;
    for (int r = r0; r < r1; r++) {
        float v = h[(size_t)r * HIDD + c];
        s += v;
        ss = fmaf(v, v, ss);
    }
    atomicAdd(&g_sum[c], s);
    atomicAdd(&g_sumsq[c], ss);
}

__global__ void k_bn_finalize(const float* __restrict__ gamma,
                              const float* __restrict__ beta) {
    int c = threadIdx.x;
    float mu = g_sum[c] * (1.f / NN);
    float var = g_sumsq[c] * (1.f / NN) - mu * mu;
    float rstd = rsqrtf(var + BN_EPS);
    float sc = rstd * gamma[c];
    g_bn_s[c] = sc;
    g_bn_t[c] = beta[c] - mu * sc;
}

// ---------------- log_softmax over 40 classes (one warp per row) ----------------
__global__ void k_logsoftmax(const float* __restrict__ in, float* __restrict__ out) {
    int warp = (blockIdx.x * blockDim.x + threadIdx.x) >> 5;
    int lane = threadIdx.x & 31;
    if (warp >= NN) return;
    const float* r = in + (size_t)warp * OUTD;
    float v0 = (lane < OUTD) ? r[lane] : -INFINITY;
    float v1 = (lane + 32 < OUTD) ? r[lane + 32] : -INFINITY;
    float m = fmaxf(v0, v1);
#pragma unroll
    for (int off = 16; off > 0; off >>= 1)
        m = fmaxf(m, __shfl_xor_sync(0xFFFFFFFFu, m, off));
    float s = 0.f;
    if (lane < OUTD)      s += expf(v0 - m);
    if (lane + 32 < OUTD) s += expf(v1 - m);
#pragma unroll
    for (int off = 16; off > 0; off >>= 1)
        s += __shfl_xor_sync(0xFFFFFFFFu, s, off);
    float l = m + logf(s);
    if (lane < OUTD)      out[(size_t)warp * OUTD + lane] = v0 - l;
    if (lane + 32 < OUTD) out[(size_t)warp * OUTD + lane + 32] = v1 - l;
}

// ---------------- launch ----------------
extern "C" void kernel_launch(void* const* d_in, const int* in_sizes, int n_in,
                              void* d_out, int out_size) {
    const float* x     = (const float*)d_in[0];
    const void*  ei    = d_in[1];
    const float* W1    = (const float*)d_in[2];
    const float* b1    = (const float*)d_in[3];
    const float* W2    = (const float*)d_in[4];
    const float* b2    = (const float*)d_in[5];
    const float* W3    = (const float*)d_in[6];
    const float* b3    = (const float*)d_in[7];
    const float* gamma = (const float*)d_in[8];
    const float* beta  = (const float*)d_in[9];
    float* out = (float*)d_out;

    float *t1, *t2;
    cudaGetSymbolAddress((void**)&t1, g_t1);
    cudaGetSymbolAddress((void**)&t2, g_t2);

    // ---- graph preprocessing ----
    k_detect<<<1, 1>>>(ei);
    k_init_counts<<<cdiv(NN, 256), 256>>>();
    k_convert_deg<<<cdiv(EE, 256), 256>>>(ei);
    k_dinv<<<cdiv(NN, 256), 256>>>();
    k_scan<<<1, 1024>>>();
    k_fill<<<cdiv(TOT, 256), 256>>>();

    dim3 g256(cdiv(HIDD, 64), cdiv(NN, 128));
    dim3 g40(cdiv(OUTD, 64), cdiv(NN, 128));

    // ---- layer 1 (aggregate-first: agg(x) @ W1 + b1 == agg(x @ W1) + b1) ----
    k_agg_v<32, false><<<NN, 32>>>(x, nullptr, t1);                        // t1 = agg(x)  [N,128]
    k_gemm_tc<false, true><<<g256, 256>>>(t1, W1, b1, t2, NN, IND, HIDD);  // t2 = t1@W1+b1
    k_zero_stats<<<1, HIDD>>>();
    k_stats<<<256, HIDD>>>(t2);
    k_bn_finalize<<<1, HIDD>>>(gamma, beta);

    // ---- layer 2 (BN+ReLU fused into GEMM A-load) ----
    k_gemm_tc<true, false><<<g256, 256>>>(t2, W2, nullptr, t1, NN, HIDD, HIDD);
    k_agg_v<64, true><<<NN, 64>>>(t1, b2, t2);
    k_zero_stats<<<1, HIDD>>>();
    k_stats<<<256, HIDD>>>(t2);
    k_bn_finalize<<<1, HIDD>>>(gamma, beta);

    // ---- layer 3 ----
    k_gemm_tc<true, false><<<g40, 256>>>(t2, W3, nullptr, t1, NN, HIDD, OUTD);
    k_agg40<<<NN, 64>>>(t1, b3, t2);

    // ---- log_softmax ----
    k_logsoftmax<<<cdiv(NN * 32, 256), 256>>>(t2, out);
}